// round 13
// baseline (speedup 1.0000x reference)
#include <cuda_runtime.h>
#include <cstdint>

// Problem constants
#define TT 128
#define SS 512
#define BB 512
#define GRID_F 148           // one CTA per SM, single wave
#define ENG 2                // 256-thread engines per CTA (512 thr -> 128 regs/thr)
#define NENG (GRID_F*ENG)    // 296 engines; each handles 2 batches -> 592 slots

__device__ float g_res[BB];  // per-batch (numerator - denominator)

__device__ __forceinline__ float fex2(float x){ float r; asm("ex2.approx.f32 %0,%1;":"=f"(r):"f"(x)); return r; }
__device__ __forceinline__ float flg2(float x){ float r; asm("lg2.approx.f32 %0,%1;":"=f"(r):"f"(x)); return r; }

#define FMA2(d,a,b,c) asm("fma.rn.f32x2 %0,%1,%2,%3;":"=l"(d):"l"(a),"l"(b),"l"(c))
#define ADD2(d,a,b)   asm("add.rn.f32x2 %0,%1,%2;":"=l"(d):"l"(a),"l"(b))
#define UNPK(lo_,hi_,v) asm("mov.b64 {%0,%1},%2;":"=f"(lo_),"=f"(hi_):"l"(v))

#define L2E 1.4426950408889634f
#define LN2 0.6931471805599453f

// ---------------------------------------------------------------------------
// Engine = 256 threads handling TWO batches, i-half split:
//   te = tid&255, col = te&127, half = te>>7. Thread owns E[i0:i0+64, col]
//   (i0 = 64*half) as 32 f32x2 register pairs (64 regs; fits 128-reg cap).
// Per step: bar; both halves GEMV their 64 rows for both batches (64 FMA2);
// half1 publishes its partial via smem; bar; half0 adds partner partial,
// does lg2/masked update/ex2, publishes p(s+1) and renormalizer K.
// 16 warps/SM from 2 independent engines (separate named barriers) keep the
// fma pipe fed through each engine's serial tail.
// ---------------------------------------------------------------------------
__global__ void __launch_bounds__(512,1) crf_forward(
    const float* __restrict__ em, const int* __restrict__ tags,
    const int* __restrict__ mask, const float* __restrict__ startt,
    const float* __restrict__ endt, const float* __restrict__ trans)
{
  __shared__ __align__(16) float pbuf[ENG][2][TT];  // [eng][batch][i]
  __shared__ float2 xbuf[ENG][TT];                  // half1 -> half0 partials
  __shared__ float  kbuf[ENG][2][2];                // [eng][batch][phase]
  __shared__ float  redf[ENG][16];
  __shared__ int    redi[ENG][8];

  const int tid  = threadIdx.x;
  const int eng  = tid >> 8;      // 0..1
  const int te   = tid & 255;     // engine-local thread
  const int col  = te & 127;      // owned state column
  const int half = te >> 7;       // i-half
  const int lane = tid & 31;
  const int wrp  = te >> 5;       // 0..7 within engine
  const int barid = eng + 1;
  const int i0   = half << 6;

  // ---- E half-column in registers: 32 f32x2 pairs (rows i0..i0+63) ----
  unsigned long long E2[32];
  #pragma unroll
  for (int q = 0; q < 32; ++q){
    float e0 = fex2(trans[(i0+2*q  )*TT + col] * L2E);
    float e1 = fex2(trans[(i0+2*q+1)*TT + col] * L2E);
    asm("mov.b64 %0,{%1,%2};":"=l"(E2[q]):"f"(e0),"f"(e1));
  }
  const float endj = endt[col];
  const float stj  = startt[col];

  const int ge  = eng*GRID_F + blockIdx.x;   // 0..295
  const int b0  = ge;
  const int b1v = ge + NENG;
  const bool has1 = (b1v < BB);
  const int b1  = has1 ? b1v : 0;            // dummy -> batch0 data, no write

  const float* e0b = em + (long long)b0*SS*TT;
  const float* e1b = em + (long long)b1*SS*TT;
  const int*   mA  = mask + b0*SS;
  const int*   mB  = mask + b1*SS;

  // ---------------- numerator (gather path scores), trivial cost -----------
  float num0 = 0.f, num1 = 0.f;
  #pragma unroll
  for (int bt = 0; bt < 2; ++bt){
    const int b = bt ? b1 : b0;
    const int*   tg  = tags + b*SS;
    const int*   mb  = bt ? mB : mA;
    const float* ebb = bt ? e1b : e0b;
    float nacc = 0.f; int ncnt = 0;
    for (int s = te; s < SS; s += 256){
      int m = mb[s];
      ncnt += (m > 0);
      if (s > 0 && m > 0){
        int tp = tg[s-1], tc = tg[s];
        nacc += trans[tp*TT + tc] + ebb[s*TT + tc];
      }
    }
    #pragma unroll
    for (int o = 16; o; o >>= 1){
      nacc += __shfl_xor_sync(0xffffffffu, nacc, o);
      ncnt += __shfl_xor_sync(0xffffffffu, ncnt, o);
    }
    if (lane == 0){ redf[eng][wrp] = nacc; redi[eng][wrp] = ncnt; }
    asm volatile("bar.sync %0,256;"::"r"(barid):"memory");
    if (te == 0){
      float na = 0.f; int nc = 0;
      #pragma unroll
      for (int w = 0; w < 8; ++w){ na += redf[eng][w]; nc += redi[eng][w]; }
      int t0 = tg[0];
      float nv = startt[t0] + ebb[t0] + na + endt[tg[nc-1]];
      if (bt) num1 = nv; else num0 = nv;
    }
    asm volatile("bar.sync %0,256;"::"r"(barid):"memory");
  }

  // ---------------- dual forward recursion ---------------------------------
  float u0 = 0.f, u1 = 0.f, C0 = 0.f, C1 = 0.f;
  float emA0 = 0.f, emB0 = 0.f, emA1 = 0.f, emB1 = 0.f;
  int   mkA0 = 0, mkB0 = 0, mkA1 = 0, mkB1 = 0;
  if (half == 0){
    u0 = stj + e0b[col];
    u1 = stj + e1b[col];
    pbuf[eng][0][col] = fex2(u0 * L2E);     // p0(1)
    pbuf[eng][1][col] = fex2(u1 * L2E);     // p1(1)
    if (te == 0){ kbuf[eng][0][0] = u0; kbuf[eng][1][0] = u1; }
    emA0 = e0b[TT + col];  emB0 = e0b[2*TT + col];
    emA1 = e1b[TT + col];  emB1 = e1b[2*TT + col];
    mkA0 = mA[1]; mkB0 = mA[2];
    mkA1 = mB[1]; mkB1 = mB[2];
  }

  const ulonglong2* pA = (const ulonglong2*)&pbuf[eng][0][i0];
  const ulonglong2* pB = (const ulonglong2*)&pbuf[eng][1][i0];

  for (int s = 1; s < SS; ++s){
    const int ph = s & 1;
    asm volatile("bar.sync %0,256;"::"r"(barid):"memory");  // p(s) ready

    // ---- GEMV over this thread's 64 rows, both batches (64 FMA2) ----
    unsigned long long c0=0,c1=0,d0=0,d1=0;
    #pragma unroll
    for (int q = 0; q < 16; ++q){
      ulonglong2 pa = pA[q];
      ulonglong2 pb = pB[q];
      FMA2(c0, E2[2*q  ], pa.x, c0);
      FMA2(c1, E2[2*q+1], pa.y, c1);
      FMA2(d0, E2[2*q  ], pb.x, d0);
      FMA2(d1, E2[2*q+1], pb.y, d1);
    }
    ADD2(c0,c0,c1); ADD2(d0,d0,d1);
    float cl,ch,dl,dh; UNPK(cl,ch,c0); UNPK(dl,dh,d0);
    float s0 = cl + ch;     // batch0 partial (this i-half)
    float s1 = dl + dh;     // batch1 partial

    float emN0 = 0.f, emN1 = 0.f; int mkN0 = 0, mkN1 = 0;
    if (half){
      xbuf[eng][col] = make_float2(s0, s1);
    } else if (s + 2 < SS){
      emN0 = e0b[(s+2)*TT + col]; emN1 = e1b[(s+2)*TT + col];
      mkN0 = mA[s+2];             mkN1 = mB[s+2];
    }

    asm volatile("bar.sync %0,256;"::"r"(barid):"memory");  // partials ready

    if (!half){
      float2 r = xbuf[eng][col];
      float acc0 = s0 + r.x;
      float acc1 = s1 + r.y;
      float K0 = kbuf[eng][0][ph^1];
      float K1 = kbuf[eng][1][ph^1];
      float v0 = fmaf(flg2(acc0), LN2, emA0);
      float v1 = fmaf(flg2(acc1), LN2, emA1);
      if (mkA0 > 0){ u0 = v0 - K0; C0 += K0; }
      if (mkA1 > 0){ u1 = v1 - K1; C1 += K1; }
      pbuf[eng][0][col] = fex2(u0 * L2E);   // p0(s+1)
      pbuf[eng][1][col] = fex2(u1 * L2E);   // p1(s+1)
      if (te == 0){ kbuf[eng][0][ph] = u0; kbuf[eng][1][ph] = u1; }
      emA0 = emB0; emB0 = emN0; mkA0 = mkB0; mkB0 = mkN0;
      emA1 = emB1; emB1 = emN1; mkA1 = mkB1; mkB1 = mkN1;
    }
  }

  // ---- final: denom_b = C + logsumexp_col(u_col + end_col), half0 only ----
  #pragma unroll
  for (int bt = 0; bt < 2; ++bt){
    float w = half ? -3.0e38f : ((bt ? u1 : u0) + endj);
    float m = w;
    #pragma unroll
    for (int o = 16; o; o >>= 1) m = fmaxf(m, __shfl_xor_sync(0xffffffffu, m, o));
    if (lane == 0) redf[eng][wrp] = m;
    asm volatile("bar.sync %0,256;"::"r"(barid):"memory");
    m = redf[eng][0];
    #pragma unroll
    for (int w2 = 1; w2 < 8; ++w2) m = fmaxf(m, redf[eng][w2]);
    float e = fex2((w - m) * L2E);          // half1: underflows to 0
    #pragma unroll
    for (int o = 16; o; o >>= 1) e += __shfl_xor_sync(0xffffffffu, e, o);
    if (lane == 0) redf[eng][8 + wrp] = e;
    asm volatile("bar.sync %0,256;"::"r"(barid):"memory");
    if (te == 0){
      float ssum = 0.f;
      #pragma unroll
      for (int w2 = 0; w2 < 8; ++w2) ssum += redf[eng][8 + w2];
      float denomv = (bt ? C1 : C0) + m + flg2(ssum) * LN2;
      if (bt){ if (has1) g_res[b1] = num1 - denomv; }
      else   { g_res[b0] = num0 - denomv; }
    }
    asm volatile("bar.sync %0,256;"::"r"(barid):"memory");
  }
}

// ---------------------------------------------------------------------------
// Deterministic final reduction: out = sum_b g_res[b]
// ---------------------------------------------------------------------------
__global__ void crf_final(float* out)
{
  __shared__ float sm[256];
  int t = threadIdx.x;
  float a = 0.f;
  for (int b = t; b < BB; b += 256) a += g_res[b];
  sm[t] = a; __syncthreads();
  #pragma unroll
  for (int o = 128; o; o >>= 1){
    if (t < o) sm[t] += sm[t + o];
    __syncthreads();
  }
  if (t == 0) out[0] = sm[0];
}

extern "C" void kernel_launch(void* const* d_in, const int* in_sizes, int n_in,
                              void* d_out, int out_size)
{
  const float* em    = (const float*)d_in[0];
  const int*   tags  = (const int*)  d_in[1];
  const int*   mask  = (const int*)  d_in[2];
  const float* st    = (const float*)d_in[3];
  const float* en    = (const float*)d_in[4];
  const float* tr    = (const float*)d_in[5];
  float* out = (float*)d_out;

  crf_forward<<<GRID_F, 512>>>(em, tags, mask, st, en, tr);
  crf_final<<<1, 256>>>(out);
}

// round 17
// speedup vs baseline: 1.6014x; 1.6014x over previous
#include <cuda_runtime.h>
#include <cstdint>

// Problem constants
#define TT 128
#define SS 512
#define BB 512
#define GRID_F 148           // one CTA per SM, single wave
#define ENG 2                // 128-thread engines per CTA (256 thr)
#define NENG (GRID_F*ENG)    // 296 engines; each handles up to 2 batches

__device__ float g_res[BB];  // per-batch (numerator - denominator)

__device__ __forceinline__ float fex2(float x){ float r; asm("ex2.approx.f32 %0,%1;":"=f"(r):"f"(x)); return r; }
__device__ __forceinline__ float flg2(float x){ float r; asm("lg2.approx.f32 %0,%1;":"=f"(r):"f"(x)); return r; }
__device__ __forceinline__ float frcp(float x){ float r; asm("rcp.approx.f32 %0,%1;":"=f"(r):"f"(x)); return r; }

#define FMA2(d,a,b,c) asm("fma.rn.f32x2 %0,%1,%2,%3;":"=l"(d):"l"(a),"l"(b),"l"(c))
#define ADD2(d,a,b)   asm("add.rn.f32x2 %0,%1,%2;":"=l"(d):"l"(a),"l"(b))
#define UNPK(lo_,hi_,v) asm("mov.b64 {%0,%1},%2;":"=f"(lo_),"=f"(hi_):"l"(v))

#define L2E 1.4426950408889634f
#define LN2 0.6931471805599453f

// ---------------------------------------------------------------------------
// Exp-domain forward recursion. Engine = 128 threads, 2 batches. Thread t
// owns column E[:,t] = exp(trans[:,t]) as 64 f32x2 register pairs.
// State: q_j(s) = exp(u_j(s)) * G(s), with per-step renormalizer
// R(s) = 1/q_0(s-1) (so G telescopes; thread 0 tracks L = -ln G = sum ln q_0
// via lg2 hidden under the GEMV). Per step (ONE barrier):
//   bar -> [read q_0 broadcast, rcp, (t0: lg2 accumulate L)]  (off-path)
//        -> GEMV acc_j = sum_i q_i E_ij (f32x2 FMAs from smem p-buffer)
//        -> q_j = acc_j * t_j * R   (t_j = exp(em_j) precomputed off-path)
//        -> masked select, store q to other phase buffer.
// No per-step lg2/ex2 on the critical path. Engines are phase-offset by a
// ~512-cycle delay so their GEMVs interleave instead of contending.
// ---------------------------------------------------------------------------
__global__ void __launch_bounds__(256,1) crf_forward(
    const float* __restrict__ em, const int* __restrict__ tags,
    const int* __restrict__ mask, const float* __restrict__ startt,
    const float* __restrict__ endt, const float* __restrict__ trans)
{
  __shared__ __align__(16) float pbuf[ENG][2][2][TT];  // [eng][batch][phase][i]
  __shared__ float red[ENG][8];

  const int tid  = threadIdx.x;
  const int eng  = tid >> 7;      // 0..1
  const int t    = tid & 127;     // owned state (column)
  const int lane = tid & 31;
  const int wrp  = t >> 5;
  const int barid = eng + 1;

  // ---- full E column in registers: 64 f32x2 pairs ----
  unsigned long long E2[64];
  #pragma unroll
  for (int q = 0; q < 64; ++q){
    float e0 = fex2(trans[(2*q  )*TT + t] * L2E);
    float e1 = fex2(trans[(2*q+1)*TT + t] * L2E);
    asm("mov.b64 %0,{%1,%2};":"=l"(E2[q]):"f"(e0),"f"(e1));
  }
  const float endj = endt[t];
  const float stj  = startt[t];

  const int ge  = eng*GRID_F + blockIdx.x;   // 0..295
  const int b0  = ge;
  const int b1v = ge + NENG;
  const bool has1 = (b1v < BB);
  const int b1  = has1 ? b1v : 0;            // dummy -> batch0 data, no write

  const float* e0b = em + (long long)b0*SS*TT;
  const float* e1b = em + (long long)b1*SS*TT;
  const int*   mA  = mask + b0*SS;
  const int*   mB  = mask + b1*SS;

  // ---------------- numerator (gather path scores), trivial cost -----------
  float num0 = 0.f, num1 = 0.f;
  #pragma unroll
  for (int bt = 0; bt < 2; ++bt){
    const int b = bt ? b1 : b0;
    const int*   tg  = tags + b*SS;
    const int*   mb  = bt ? mB : mA;
    const float* ebb = bt ? e1b : e0b;
    float nacc = 0.f; int ncnt = 0;
    for (int s = t; s < SS; s += TT){
      int m = mb[s];
      ncnt += (m > 0);
      if (s > 0 && m > 0){
        int tp = tg[s-1], tc = tg[s];
        nacc += trans[tp*TT + tc] + ebb[s*TT + tc];
      }
    }
    #pragma unroll
    for (int o = 16; o; o >>= 1){
      nacc += __shfl_xor_sync(0xffffffffu, nacc, o);
      ncnt += __shfl_xor_sync(0xffffffffu, ncnt, o);
    }
    if (lane == 0){ red[eng][wrp] = nacc; ((int*)&red[eng][4])[wrp] = ncnt; }
    asm volatile("bar.sync %0,128;"::"r"(barid):"memory");
    if (t == 0){
      float na = red[eng][0] + red[eng][1] + red[eng][2] + red[eng][3];
      int   nc = ((int*)&red[eng][4])[0] + ((int*)&red[eng][4])[1]
               + ((int*)&red[eng][4])[2] + ((int*)&red[eng][4])[3];
      int t0 = tg[0];
      float nv = startt[t0] + ebb[t0] + na + endt[tg[nc-1]];
      if (bt) num1 = nv; else num0 = nv;
    }
    asm volatile("bar.sync %0,128;"::"r"(barid):"memory");
  }

  // ---------------- exp-domain recursion init ------------------------------
  float q0r = fex2((stj + e0b[t]) * L2E);   // q(0) = exp(u(0))
  float q1r = fex2((stj + e1b[t]) * L2E);
  pbuf[eng][0][0][t] = q0r;
  pbuf[eng][1][0][t] = q1r;
  float L0 = 0.f, L1 = 0.f;                 // -ln G (thread 0 only meaningful)

  // pipeline: tA = exp(em(s=1)); emB raw em(s=2); masks
  float tA0 = fex2(e0b[TT + t] * L2E);
  float tA1 = fex2(e1b[TT + t] * L2E);
  float emB0 = e0b[2*TT + t], emB1 = e1b[2*TT + t];
  int   mkA0 = mA[1], mkA1 = mB[1];
  int   mkB0 = mA[2], mkB1 = mB[2];

  // phase-offset engine 1 by ~512 cycles (dependent FMA chain)
  if (eng == 1){
    float x = 1.0f;
    #pragma unroll 1
    for (int i = 0; i < 128; ++i)
      asm volatile("fma.rn.f32 %0,%0,%1,%0;" : "+f"(x) : "f"(0.0f));
  }

  for (int s = 1; s < SS; ++s){
    const int rp = (s-1) & 1;       // read phase (q(s-1))
    const int wp = s & 1;           // write phase (q(s))
    asm volatile("bar.sync %0,128;"::"r"(barid):"memory");  // q(s-1) visible

    // renormalizer inputs (broadcast LDS + MUFU, hidden under GEMV)
    float pz0 = pbuf[eng][0][rp][0];
    float pz1 = pbuf[eng][1][rp][0];
    float R0 = frcp(pz0);
    float R1 = frcp(pz1);
    if (t == 0){
      if (mkA0 > 0) L0 += flg2(pz0) * LN2;
      if (mkA1 > 0) L1 += flg2(pz1) * LN2;
    }

    // ---- GEMV: acc_j = sum_i q_i(s-1) * E_ij, both batches ----
    const ulonglong2* pA = (const ulonglong2*)&pbuf[eng][0][rp][0];
    const ulonglong2* pB = (const ulonglong2*)&pbuf[eng][1][rp][0];
    unsigned long long c0=0,c1=0,c2=0,c3=0, d0=0,d1=0,d2=0,d3=0;
    #pragma unroll
    for (int q = 0; q < 32; ++q){
      ulonglong2 a = pA[q];
      ulonglong2 b = pB[q];
      if (q & 1){
        FMA2(c2, E2[2*q], a.x, c2); FMA2(c3, E2[2*q+1], a.y, c3);
        FMA2(d2, E2[2*q], b.x, d2); FMA2(d3, E2[2*q+1], b.y, d3);
      } else {
        FMA2(c0, E2[2*q], a.x, c0); FMA2(c1, E2[2*q+1], a.y, c1);
        FMA2(d0, E2[2*q], b.x, d0); FMA2(d1, E2[2*q+1], b.y, d1);
      }
    }
    ADD2(c0,c0,c2); ADD2(c1,c1,c3); ADD2(c0,c0,c1);
    ADD2(d0,d0,d2); ADD2(d1,d1,d3); ADD2(d0,d0,d1);
    float cl,ch,dl,dh; UNPK(cl,ch,c0); UNPK(dl,dh,d0);
    float acc0 = cl + ch;
    float acc1 = dl + dh;

    // ---- exp-domain update: q = acc * t * R (masked) ----
    float pn0 = acc0 * tA0 * R0;
    float pn1 = acc1 * tA1 * R1;
    if (mkA0 > 0) q0r = pn0;
    if (mkA1 > 0) q1r = pn1;
    pbuf[eng][0][wp][t] = q0r;
    pbuf[eng][1][wp][t] = q1r;

    // rotate emission/mask pipeline (off critical path)
    tA0 = fex2(emB0 * L2E);
    tA1 = fex2(emB1 * L2E);
    mkA0 = mkB0; mkA1 = mkB1;
    if (s + 2 < SS){
      emB0 = e0b[(s+2)*TT + t]; emB1 = e1b[(s+2)*TT + t];
      mkB0 = mA[s+2];           mkB1 = mB[s+2];
    }
  }

  // ---- finals: u_j = ln q_j(511); denom = L + logsumexp_j(u_j + end_j) ----
  float u0 = flg2(q0r) * LN2;
  float u1 = flg2(q1r) * LN2;
  #pragma unroll
  for (int bt = 0; bt < 2; ++bt){
    float w = (bt ? u1 : u0) + endj;
    float m = w;
    #pragma unroll
    for (int o = 16; o; o >>= 1) m = fmaxf(m, __shfl_xor_sync(0xffffffffu, m, o));
    if (lane == 0) red[eng][wrp] = m;
    asm volatile("bar.sync %0,128;"::"r"(barid):"memory");
    m = fmaxf(fmaxf(red[eng][0], red[eng][1]), fmaxf(red[eng][2], red[eng][3]));
    float e = fex2((w - m) * L2E);
    #pragma unroll
    for (int o = 16; o; o >>= 1) e += __shfl_xor_sync(0xffffffffu, e, o);
    if (lane == 0) red[eng][4 + wrp] = e;
    asm volatile("bar.sync %0,128;"::"r"(barid):"memory");
    if (t == 0){
      float ssum = red[eng][4] + red[eng][5] + red[eng][6] + red[eng][7];
      float denomv = (bt ? L1 : L0) + m + flg2(ssum) * LN2;
      if (bt){ if (has1) g_res[b1] = num1 - denomv; }
      else   { g_res[b0] = num0 - denomv; }
    }
    asm volatile("bar.sync %0,128;"::"r"(barid):"memory");
  }
}

// ---------------------------------------------------------------------------
// Deterministic final reduction: out = sum_b g_res[b]
// ---------------------------------------------------------------------------
__global__ void crf_final(float* out)
{
  __shared__ float sm[256];
  int t = threadIdx.x;
  float a = 0.f;
  for (int b = t; b < BB; b += 256) a += g_res[b];
  sm[t] = a; __syncthreads();
  #pragma unroll
  for (int o = 128; o; o >>= 1){
    if (t < o) sm[t] += sm[t + o];
    __syncthreads();
  }
  if (t == 0) out[0] = sm[0];
}

extern "C" void kernel_launch(void* const* d_in, const int* in_sizes, int n_in,
                              void* d_out, int out_size)
{
  const float* em    = (const float*)d_in[0];
  const int*   tags  = (const int*)  d_in[1];
  const int*   mask  = (const int*)  d_in[2];
  const float* st    = (const float*)d_in[3];
  const float* en    = (const float*)d_in[4];
  const float* tr    = (const float*)d_in[5];
  float* out = (float*)d_out;

  crf_forward<<<GRID_F, 256>>>(em, tags, mask, st, en, tr);
  crf_final<<<1, 256>>>(out);
}